// round 16
// baseline (speedup 1.0000x reference)
#include <cuda_runtime.h>
#include <cuda_fp16.h>
#include <math.h>
#include <stdint.h>

// ---------------- problem constants ----------------
#define Bn    2
#define Ln    2048
#define Dn    2048
#define DINn  4096
#define Nn    128
#define Hn    64
#define Pn    64
#define Kc    4
#define CONVD 4352            // DIN + 2*G*N
#define Qn    64
#define NCn   32
#define PROJW 8512            // 2*DIN + 2*G*N + H
#define DTOFF 8448            // DIN + CONVD
#define BLn   (Bn*Ln)         // 4096
#define EPSf  1e-5f

// GEMM tiling: 128(M) x 256(N) block tile, BK=64, 512 threads, fp16 single-pass
#define A_CH  16384
#define B_CH  32768
#define NSTAGE 4

#define NCH1  32
#define NT1   33              // 33*256 = 8448: z + xBC only (dt handled by k_dtproj)
#define NTB1  34
#define NCH2  64
#define MTil  32

// ---------------- scratch ----------------
__device__ float g_h[(size_t)BLn*Dn];
__device__ float g_proj[(size_t)BLn*PROJW];
__device__ __half g_xbc[(size_t)BLn*CONVD];
__device__ float g_dt[(size_t)BLn*Hn];
__device__ float g_a[(size_t)BLn*Hn];
__device__ float g_acs[(size_t)BLn*Hn];
__device__ float g_csum[(size_t)Bn*Hn*NCn];
__device__ float g_states[(size_t)Bn*Hn*NCn*Pn*Nn];
__device__ __align__(16) unsigned char g_statein[(size_t)Bn*Hn*NCn*16384]; // fp16 swizzled tiles
__device__ float g_y[(size_t)BLn*DINn];

__device__ __align__(1024) unsigned char g_Af[(size_t)MTil*NCH2*A_CH];
__device__ __align__(1024) unsigned char g_Bf[(size_t)NTB1*NCH1*B_CH];

// ---------------- PTX helpers ----------------
__device__ __forceinline__ uint32_t smem_u32(const void* p) {
    uint32_t a;
    asm("{ .reg .u64 t; cvta.to.shared.u64 t, %1; cvt.u32.u64 %0, t; }" : "=r"(a) : "l"(p));
    return a;
}
__device__ __forceinline__ uint32_t swz128(uint32_t o) { return o ^ ((o >> 3) & 0x70); }

#define MBAR_INIT(a, c) \
    asm volatile("mbarrier.init.shared.b64 [%0], %1;" :: "r"(a), "r"(c) : "memory")
#define MBAR_EXPECT_TX(a, b) \
    asm volatile("mbarrier.arrive.expect_tx.shared.b64 _, [%0], %1;" :: "r"(a), "r"(b) : "memory")
#define MBAR_WAIT(a, ph) do { \
    uint32_t _m = (a); uint32_t _p = (ph); uint32_t _d; \
    asm volatile("{\n\t.reg .pred p;\n\t" \
        "mbarrier.try_wait.parity.acquire.cta.shared::cta.b64 p, [%1], %2;\n\t" \
        "selp.b32 %0, 1, 0, p;\n\t}" : "=r"(_d) : "r"(_m), "r"(_p) : "memory"); \
    if (!_d) { \
        asm volatile("{\n\t.reg .pred P1;\n\t" \
            "WL_%=:\n\t" \
            "mbarrier.try_wait.parity.acquire.cta.shared::cta.b64 P1, [%0], %1, 0x989680;\n\t" \
            "@P1 bra.uni WD_%=;\n\t" \
            "bra.uni WL_%=;\n\t" \
            "WD_%=:\n\t}" :: "r"(_m), "r"(_p) : "memory"); \
    } \
} while (0)

#define BULK_LD(sa, gp, bytes, mb) \
    asm volatile("cp.async.bulk.shared::cluster.global.mbarrier::complete_tx::bytes [%0], [%1], %2, [%3];" \
        :: "r"(sa), "l"(gp), "r"(bytes), "r"(mb) : "memory")

#define LDSMX4(r, addr) \
    asm volatile("ldmatrix.sync.aligned.m8n8.x4.shared.b16 {%0,%1,%2,%3}, [%4];" \
        : "=r"((r)[0]), "=r"((r)[1]), "=r"((r)[2]), "=r"((r)[3]) : "r"(addr))

#define MMA_FP16(d, a, b0, b1) \
    asm volatile("mma.sync.aligned.m16n8k16.row.col.f32.f16.f16.f32 " \
        "{%0,%1,%2,%3}, {%4,%5,%6,%7}, {%8,%9}, {%0,%1,%2,%3};" \
        : "+f"((d)[0]), "+f"((d)[1]), "+f"((d)[2]), "+f"((d)[3]) \
        : "r"((a)[0]), "r"((a)[1]), "r"((a)[2]), "r"((a)[3]), "r"(b0), "r"(b1))

// ---------------- misc helpers ----------------
__device__ __forceinline__ float block_reduce_sum(float v) {
    __shared__ float red[32];
    int lane = threadIdx.x & 31, wid = threadIdx.x >> 5;
    #pragma unroll
    for (int o = 16; o; o >>= 1) v += __shfl_down_sync(0xffffffffu, v, o);
    if (lane == 0) red[wid] = v;
    __syncthreads();
    v = (threadIdx.x < (blockDim.x >> 5)) ? red[threadIdx.x] : 0.f;
    if (wid == 0) {
        #pragma unroll
        for (int o = 16; o; o >>= 1) v += __shfl_down_sync(0xffffffffu, v, o);
        if (lane == 0) red[0] = v;
    }
    __syncthreads();
    return red[0];
}
__device__ __forceinline__ float siluf(float x) { return x / (1.f + expf(-x)); }

__device__ __forceinline__ uint32_t pack2h(float x0, float x1) {
    __half h0 = __float2half_rn(x0);
    __half h1 = __float2half_rn(x1);
    return ((uint32_t)__half_as_ushort(h1) << 16) | __half_as_ushort(h0);
}

// ---------------- 1) resid + rmsnorm -> fp32 g_h + fp16 A tiles ----------------
__global__ __launch_bounds__(256) void k_add_rmsnorm_split(
    const float* __restrict__ hs, const float* __restrict__ res,
    const float* __restrict__ w, float* __restrict__ resid_out,
    unsigned char* __restrict__ Af) {
    size_t row = blockIdx.x;
    int t = threadIdx.x;
    const float4* ph = (const float4*)(hs + row * Dn);
    const float4* pr = (const float4*)(res + row * Dn);
    float4* po = (float4*)(resid_out + row * Dn);
    float v[8];
    float ss = 0.f;
    #pragma unroll
    for (int i = 0; i < 2; i++) {
        float4 a = ph[t * 2 + i], b = pr[t * 2 + i];
        float4 x = make_float4(a.x + b.x, a.y + b.y, a.z + b.z, a.w + b.w);
        po[t * 2 + i] = x;
        v[i * 4 + 0] = x.x; v[i * 4 + 1] = x.y; v[i * 4 + 2] = x.z; v[i * 4 + 3] = x.w;
        ss += x.x * x.x + x.y * x.y + x.z * x.z + x.w * x.w;
    }
    float tot = block_reduce_sum(ss);
    float inv = rsqrtf(tot / (float)Dn + EPSf);
    int mt = (int)(row >> 7), r = (int)(row & 127);
    size_t tb = (size_t)mt * NCH1 * A_CH;
    float4* gh = (float4*)(g_h + row * Dn);
    #pragma unroll
    for (int i = 0; i < 2; i++) {
        float4 x = make_float4(v[i*4]*inv*w[t*8+i*4], v[i*4+1]*inv*w[t*8+i*4+1],
                               v[i*4+2]*inv*w[t*8+i*4+2], v[i*4+3]*inv*w[t*8+i*4+3]);
        gh[t * 2 + i] = x;
        v[i*4] = x.x; v[i*4+1] = x.y; v[i*4+2] = x.z; v[i*4+3] = x.w;
    }
    #pragma unroll
    for (int j = 0; j < 4; j++) {
        int k = t * 8 + j * 2;
        uint32_t u = pack2h(v[j * 2], v[j * 2 + 1]);
        int kc = k >> 6, c = k & 63;
        size_t off = tb + (size_t)kc * A_CH + swz128((uint32_t)(r * 128 + c * 2));
        *(uint32_t*)(Af + off) = u;
    }
}

// ---------------- weight transpose to fp16 ----------------
__global__ __launch_bounds__(256) void k_splitB(
    const float* __restrict__ W, unsigned char* __restrict__ Bf, int Nreal, int nch) {
    __shared__ float tile[64][33];
    int kb = blockIdx.y * 64;
    int n0 = blockIdx.x * 32;
    int t = threadIdx.x;
    int tx = t & 31, ty = t >> 5;
    #pragma unroll
    for (int i = 0; i < 8; i++) {
        int k = ty + i * 8;
        tile[k][tx] = W[(size_t)(kb + k) * Nreal + n0 + tx];
    }
    __syncthreads();
    int kc = kb >> 6;
    #pragma unroll
    for (int j = 0; j < 4; j++) {
        int nl = ty * 4 + j;
        int n = n0 + nl;
        uint32_t u = pack2h(tile[tx * 2][nl], tile[tx * 2 + 1][nl]);
        int nt = n >> 8, r = n & 255;
        size_t base = ((size_t)(nt * nch + kc)) * B_CH;
        size_t off = base + swz128((uint32_t)(r * 128 + tx * 4));
        *(uint32_t*)(Bf + off) = u;
    }
}

// ---------------- fp16 GEMM: 4-stage, paired-chunk (R13-proven) ----------------
__global__ __launch_bounds__(512) void gemm_mma_fp16(
    const unsigned char* __restrict__ Af, const unsigned char* __restrict__ Bf,
    float* __restrict__ C, int Nreal, int nch) {
    constexpr int STGB = 16384 + 32768;
    extern __shared__ unsigned char smg[];
    uint32_t sb = (smem_u32(smg) + 1023) & ~1023u;
    uint32_t ctrl = sb + NSTAGE * STGB;
    int t = threadIdx.x, lane = t & 31, wid = t >> 5;
    int bx = blockIdx.x, by = blockIdx.y;

    if (t == 0) {
        MBAR_INIT(ctrl + 0, 1); MBAR_INIT(ctrl + 8, 1);
        MBAR_INIT(ctrl + 16, 1); MBAR_INIT(ctrl + 24, 1);
    }
    __syncthreads();

    const unsigned char* Ap = Af + (size_t)by * nch * A_CH;
    const unsigned char* Bp = Bf + (size_t)bx * nch * B_CH;

    int wm = wid & 1, wn = wid >> 1;
    int rowA = wm * 64 + (lane & 7) + ((lane >> 3) & 1) * 8;
    int colA = ((lane >> 4) & 1) * 16;
    int rowB = wn * 32 + (lane & 7) + ((lane >> 4) & 1) * 8;
    int colB = ((lane >> 3) & 1) * 16;

    float acc[4][4][4];
    #pragma unroll
    for (int i = 0; i < 4; i++)
        #pragma unroll
        for (int j = 0; j < 4; j++)
            #pragma unroll
            for (int q = 0; q < 4; q++) acc[i][j][q] = 0.f;

    if (t == 0) {
        #pragma unroll
        for (int pc = 0; pc < 4; pc++) {
            MBAR_EXPECT_TX(ctrl + pc * 8, STGB);
            BULK_LD(sb + pc * STGB + 0,     Ap + (size_t)pc * A_CH, A_CH, ctrl + pc * 8);
            BULK_LD(sb + pc * STGB + 16384, Bp + (size_t)pc * B_CH, B_CH, ctrl + pc * 8);
        }
    }
    int ph[NSTAGE] = {0, 0, 0, 0};
    for (int kc = 0; kc < nch; kc += 2) {
        #pragma unroll
        for (int half = 0; half < 2; half++) {
            int slot = (kc + half) % NSTAGE;
            MBAR_WAIT(ctrl + slot * 8, ph[slot]);
            ph[slot] ^= 1;
            uint32_t s = sb + slot * STGB;
            uint32_t sA = s, sB = s + 16384;
            #pragma unroll
            for (int k = 0; k < 4; k++) {
                uint32_t bh[2][4];
                #pragma unroll
                for (int ib = 0; ib < 2; ib++) {
                    uint32_t off = swz128((uint32_t)((rowB + ib * 16) * 128 + k * 32 + colB));
                    LDSMX4(bh[ib], sB + off);
                }
                #pragma unroll
                for (int im = 0; im < 4; im++) {
                    uint32_t ah[4];
                    uint32_t off = swz128((uint32_t)((rowA + im * 16) * 128 + k * 32 + colA));
                    LDSMX4(ah, sA + off);
                    #pragma unroll
                    for (int ib = 0; ib < 2; ib++)
                        #pragma unroll
                        for (int hf = 0; hf < 2; hf++)
                            MMA_FP16(acc[im][ib * 2 + hf], ah, bh[ib][2 * hf], bh[ib][2 * hf + 1]);
                }
            }
        }
        __syncthreads();
        if (t == 0) {
            #pragma unroll
            for (int half = 0; half < 2; half++) {
                int nc = kc + 4 + half;
                if (nc < nch) {
                    int ns = nc % NSTAGE;
                    uint32_t d = sb + ns * STGB;
                    uint32_t mb = ctrl + ns * 8;
                    MBAR_EXPECT_TX(mb, STGB);
                    BULK_LD(d + 0,     Ap + (size_t)nc * A_CH, A_CH, mb);
                    BULK_LD(d + 16384, Bp + (size_t)nc * B_CH, B_CH, mb);
                }
            }
        }
    }

    int mBase = by * 128 + wm * 64;
    int nBase = bx * 256 + wn * 32;
    #pragma unroll
    for (int im = 0; im < 4; im++) {
        #pragma unroll
        for (int in = 0; in < 4; in++) {
            int r = mBase + im * 16 + (lane >> 2);
            int c = nBase + in * 8 + (lane & 3) * 2;
            if (c < Nreal) {
                float2 v0 = make_float2(acc[im][in][0], acc[im][in][1]);
                float2 v1 = make_float2(acc[im][in][2], acc[im][in][3]);
                *(float2*)(C + (size_t)r * Nreal + c) = v0;
                *(float2*)(C + (size_t)(r + 8) * Nreal + c) = v1;
            }
        }
    }
}

// ---------------- exact fp32 skinny GEMM for dt columns + softplus ----------------
__global__ __launch_bounds__(256) void k_dtproj(
    const float* __restrict__ ipw, const float* __restrict__ dtb,
    const float* __restrict__ alog) {
    __shared__ float sh[64][68];
    __shared__ float sw[64][68];
    int m0 = blockIdx.x * 64;
    int t = threadIdx.x;
    int tm = t >> 4, tn = t & 15;
    float acc[4][4];
    #pragma unroll
    for (int i = 0; i < 4; i++)
        #pragma unroll
        for (int j = 0; j < 4; j++) acc[i][j] = 0.f;

    for (int kb = 0; kb < Dn; kb += 64) {
        #pragma unroll
        for (int i = 0; i < 16; i++) {
            int idx = t + i * 256;
            int m = idx >> 6, kk = idx & 63;
            sh[kk][m] = g_h[(size_t)(m0 + m) * Dn + kb + kk];
        }
        #pragma unroll
        for (int i = 0; i < 16; i++) {
            int idx = t + i * 256;
            int kk = idx >> 6, h = idx & 63;
            sw[kk][h] = ipw[(size_t)(kb + kk) * PROJW + DTOFF + h];
        }
        __syncthreads();
        #pragma unroll 8
        for (int kk = 0; kk < 64; kk++) {
            float4 ar = *(const float4*)&sh[kk][tm * 4];
            float4 br = *(const float4*)&sw[kk][tn * 4];
            float a4[4] = {ar.x, ar.y, ar.z, ar.w};
            float b4[4] = {br.x, br.y, br.z, br.w};
            #pragma unroll
            for (int i = 0; i < 4; i++)
                #pragma unroll
                for (int j = 0; j < 4; j++) acc[i][j] = fmaf(a4[i], b4[j], acc[i][j]);
        }
        __syncthreads();
    }
    #pragma unroll
    for (int i = 0; i < 4; i++) {
        int m = m0 + tm * 4 + i;
        #pragma unroll
        for (int j = 0; j < 4; j++) {
            int h = tn * 4 + j;
            float x = acc[i][j] + dtb[h];
            float sp = (x > 20.f) ? x : log1pf(expf(x));
            g_dt[(size_t)m * Hn + h] = sp;
            g_a[(size_t)m * Hn + h] = -expf(alog[h]) * sp;
        }
    }
}

// ---------------- 3) causal depthwise conv -> fp16 g_xbc ----------------
__global__ __launch_bounds__(256) void k_conv2(
    const float* __restrict__ cw, const float* __restrict__ cb) {
    int bid = blockIdx.x;
    int c = (bid % 17) * 256 + threadIdx.x;
    int lblk = (bid / 17) & 127;
    int b = bid / (17 * 128);
    int l0 = lblk * 16;
    float w0 = cw[c * 4 + 0], w1 = cw[c * 4 + 1], w2 = cw[c * 4 + 2], w3 = cw[c * 4 + 3];
    float bias = cb[c];
    float x[19];
    #pragma unroll
    for (int i = 0; i < 19; i++) {
        int ls = l0 - 3 + i;
        x[i] = (ls >= 0) ? g_proj[((size_t)(b * Ln + ls)) * PROJW + DINn + c] : 0.f;
    }
    #pragma unroll
    for (int j = 0; j < 16; j++) {
        float acc = fmaf(w0, x[j], fmaf(w1, x[j + 1], fmaf(w2, x[j + 2], fmaf(w3, x[j + 3], bias))));
        g_xbc[((size_t)(b * Ln + l0 + j)) * CONVD + c] = __float2half_rn(siluf(acc));
    }
}

// ---------------- 5) per-chunk SSD via HMMA ----------------
#define KC_B   0
#define KC_C   16384
#define KC_BT  32768
#define KC_XT  49152
#define KC_XDT 57344
#define KC_M   65536
#define KC_ACS 73728
#define KC_DEC 73984
#define KC_WS  74240
#define KC_SMEM 74496

__global__ __launch_bounds__(256) void k_chunk(const float* __restrict__ dskip) {
    extern __shared__ unsigned char smc[];
    uint32_t sb = smem_u32(smc);
    float* Acs = (float*)(smc + KC_ACS);
    float* Dec = (float*)(smc + KC_DEC);
    float* WS  = (float*)(smc + KC_WS);

    int c = blockIdx.x, h = blockIdx.y, b = blockIdx.z;
    int t = threadIdx.x, lane = t & 31, wid = t >> 5;
    size_t rowbase = ((size_t)(b * Ln + c * Qn)) * CONVD;

    // B/C tiles: raw uint32 (half2) copies
    for (int i = t; i < 64 * 64; i += 256) {
        int s = i >> 6, cp = i & 63;
        size_t g = rowbase + (size_t)s * CONVD + DINn + cp * 2;
        uint32_t bu = *(const uint32_t*)(g_xbc + g);
        uint32_t cu = *(const uint32_t*)(g_xbc + g + Nn);
        int chunk = cp >> 5;
        uint32_t off = chunk * 8192 + swz128((uint32_t)(s * 128 + (cp & 31) * 4));
        *(uint32_t*)(smc + KC_B + off) = bu;
        *(uint32_t*)(smc + KC_C + off) = cu;
    }
    // warp-parallel inclusive scan of a -> Acs (2 warps cover 64 elems)
    float xv = 0.f;
    if (t < Qn) {
        xv = g_a[(size_t)(b * Ln + c * Qn + t) * Hn + h];
        #pragma unroll
        for (int o = 1; o < 32; o <<= 1) {
            float y = __shfl_up_sync(0xffffffffu, xv, o);
            if ((t & 31) >= o) xv += y;
        }
        if ((t & 31) == 31) WS[t >> 5] = xv;
    }
    __syncthreads();   // covers B/C fill + WS
    if (t < Qn) {
        if (t >= 32) xv += WS[0];
        Acs[t] = xv;
    }
    __syncthreads();
    if (t < Qn) {
        float aq = Acs[t];
        Dec[t] = expf(Acs[Qn - 1] - aq);
        g_acs[(size_t)(b * Ln + c * Qn + t) * Hn + h] = aq;
        if (t == Qn - 1) g_csum[(size_t)(b * Hn + h) * NCn + c] = aq;
    }
    // BT tile [n][q] built from the smem B tile (B synced at first barrier)
    for (int i = t; i < 128 * 32; i += 256) {
        int n = i >> 5, q2 = (i & 31) * 2;
        int chunk = n >> 6, nc = n & 63;
        __half b0 = *(const __half*)(smc + KC_B + chunk * 8192 +
                                     swz128((uint32_t)(q2 * 128 + nc * 2)));
        __half b1 = *(const __half*)(smc + KC_B + chunk * 8192 +
                                     swz128((uint32_t)((q2 + 1) * 128 + nc * 2)));
        uint32_t u = ((uint32_t)__half_as_ushort(b1) << 16) | __half_as_ushort(b0);
        *(uint32_t*)(smc + KC_BT + swz128((uint32_t)(n * 128 + q2 * 2))) = u;
    }
    __syncthreads();
    for (int i = t; i < 64 * 32; i += 256) {
        int p = i & 63, sp = (i >> 6) * 2;
        float x0 = __half2float(g_xbc[rowbase + (size_t)sp * CONVD + h * Pn + p])
                 * g_dt[(size_t)(b * Ln + c * Qn + sp) * Hn + h];
        float x1 = __half2float(g_xbc[rowbase + (size_t)(sp + 1) * CONVD + h * Pn + p])
                 * g_dt[(size_t)(b * Ln + c * Qn + sp + 1) * Hn + h];
        uint32_t off = swz128((uint32_t)(p * 128 + sp * 2));
        *(uint32_t*)(smc + KC_XT + off) = pack2h(x0, x1);
        *(uint32_t*)(smc + KC_XDT + off) = pack2h(x0 * Dec[sp], x1 * Dec[sp + 1]);
    }
    __syncthreads();

    int wq = wid & 3, ws = wid >> 2;
    int rA = wq * 16 + (lane & 7) + ((lane >> 3) & 1) * 8;
    int cA = ((lane >> 4) & 1) * 16;
    int rB = ws * 32 + (lane & 7) + ((lane >> 4) & 1) * 8;
    int cB = ((lane >> 3) & 1) * 16;

    // --- M = C @ B^T ---
    float mAcc[4][4];
    #pragma unroll
    for (int i = 0; i < 4; i++)
        #pragma unroll
        for (int j = 0; j < 4; j++) mAcc[i][j] = 0.f;
    #pragma unroll
    for (int ch = 0; ch < 2; ch++) {
        #pragma unroll
        for (int k = 0; k < 4; k++) {
            uint32_t ah[4];
            LDSMX4(ah, sb + KC_C + ch * 8192 + swz128((uint32_t)(rA * 128 + k * 32 + cA)));
            uint32_t bh[2][4];
            #pragma unroll
            for (int ib = 0; ib < 2; ib++)
                LDSMX4(bh[ib], sb + KC_B + ch * 8192 +
                       swz128((uint32_t)((rB + ib * 16) * 128 + k * 32 + cB)));
            #pragma unroll
            for (int ib = 0; ib < 2; ib++)
                #pragma unroll
                for (int hf = 0; hf < 2; hf++)
                    MMA_FP16(mAcc[ib * 2 + hf], ah, bh[ib][2 * hf], bh[ib][2 * hf + 1]);
        }
    }
    {
        int q0 = wq * 16 + (lane >> 2);
        int sc0 = ws * 32 + (lane & 3) * 2;
        #pragma unroll
        for (int nt = 0; nt < 4; nt++) {
            int sc = sc0 + nt * 8;
            #pragma unroll
            for (int r2 = 0; r2 < 2; r2++) {
                int q = q0 + r2 * 8;
                float aq = Acs[q];
                float v0 = (sc <= q)     ? mAcc[nt][r2 * 2 + 0] * expf(aq - Acs[sc])     : 0.f;
                float v1 = (sc + 1 <= q) ? mAcc[nt][r2 * 2 + 1] * expf(aq - Acs[sc + 1]) : 0.f;
                *(uint32_t*)(smc + KC_M + swz128((uint32_t)(q * 128 + sc * 2))) = pack2h(v0, v1);
            }
        }
    }
    __syncthreads();

    // --- Y_diag = Ms @ XdT^T + D_skip*xs ---
    {
        float yAcc[4][4];
        #pragma unroll
        for (int i = 0; i < 4; i++)
            #pragma unroll
            for (int j = 0; j < 4; j++) yAcc[i][j] = 0.f;
        #pragma unroll
        for (int k = 0; k < 4; k++) {
            uint32_t ah[4];
            LDSMX4(ah, sb + KC_M + swz128((uint32_t)(rA * 128 + k * 32 + cA)));
            uint32_t bh[2][4];
            #pragma unroll
            for (int ib = 0; ib < 2; ib++)
                LDSMX4(bh[ib], sb + KC_XT +
                       swz128((uint32_t)((rB + ib * 16) * 128 + k * 32 + cB)));
            #pragma unroll
            for (int ib = 0; ib < 2; ib++)
                #pragma unroll
                for (int hf = 0; hf < 2; hf++)
                    MMA_FP16(yAcc[ib * 2 + hf], ah, bh[ib][2 * hf], bh[ib][2 * hf + 1]);
        }
        float dsk = dskip[h];
        int q0 = wq * 16 + (lane >> 2);
        int p0 = ws * 32 + (lane & 3) * 2;
        #pragma unroll
        for (int nt = 0; nt < 4; nt++) {
            int p = p0 + nt * 8;
            #pragma unroll
            for (int r2 = 0; r2 < 2; r2++) {
                int q = q0 + r2 * 8;
                __half2 xsh = *(const __half2*)(g_xbc + rowbase + (size_t)q * CONVD + h * Pn + p);
                float2 xs2 = __half22float2(xsh);
                float2 o;
                o.x = yAcc[nt][r2 * 2 + 0] + dsk * xs2.x;
                o.y = yAcc[nt][r2 * 2 + 1] + dsk * xs2.y;
                *(float2*)(g_y + ((size_t)(b * Ln + c * Qn + q) * Hn + h) * Pn + p) = o;
            }
        }
    }

    // --- states = XdDT @ BT^T ---
    {
        float sAcc[8][4];
        #pragma unroll
        for (int i = 0; i < 8; i++)
            #pragma unroll
            for (int j = 0; j < 4; j++) sAcc[i][j] = 0.f;
        int rBs = ws * 64 + (lane & 7) + ((lane >> 4) & 1) * 8;
        #pragma unroll
        for (int k = 0; k < 4; k++) {
            uint32_t ah[4];
            LDSMX4(ah, sb + KC_XDT + swz128((uint32_t)(rA * 128 + k * 32 + cA)));
            uint32_t bh[4][4];
            #pragma unroll
            for (int ib = 0; ib < 4; ib++)
                LDSMX4(bh[ib], sb + KC_BT +
                       swz128((uint32_t)((rBs + ib * 16) * 128 + k * 32 + cB)));
            #pragma unroll
            for (int ib = 0; ib < 4; ib++)
                #pragma unroll
                for (int hf = 0; hf < 2; hf++)
                    MMA_FP16(sAcc[ib * 2 + hf], ah, bh[ib][2 * hf], bh[ib][2 * hf + 1]);
        }
        size_t base = ((size_t)(b * Hn + h) * NCn + c) * (Pn * Nn);
        int p0 = wq * 16 + (lane >> 2);
        int n0 = ws * 64 + (lane & 3) * 2;
        #pragma unroll
        for (int nt = 0; nt < 8; nt++) {
            int n = n0 + nt * 8;
            #pragma unroll
            for (int r2 = 0; r2 < 2; r2++) {
                int p = p0 + r2 * 8;
                float2 o = make_float2(sAcc[nt][r2 * 2 + 0], sAcc[nt][r2 * 2 + 1]);
                *(float2*)(g_states + base + (size_t)p * Nn + n) = o;
            }
        }
    }
}

// ---------------- 6) chunk-level scan -> fp16 swizzled statein tiles ----------------
__global__ __launch_bounds__(256) void k_scan() {
    int bh = blockIdx.x;
    int idx = blockIdx.y * 256 + threadIdx.x;
    int p = idx >> 6, np = idx & 63;
    int chn = np >> 5;
    uint32_t soff = chn * 8192 + swz128((uint32_t)(p * 128 + (np & 31) * 4));
    float S0 = 0.f, S1 = 0.f;
    for (int c = 0; c < NCn; c++) {
        size_t basef = ((size_t)bh * NCn + c) * (Pn * Nn);
        size_t baseb = ((size_t)bh * NCn + c) * 16384;
        *(uint32_t*)(g_statein + baseb + soff) = pack2h(S0, S1);
        float f = expf(g_csum[(size_t)bh * NCn + c]);
        float2 st = *(const float2*)(g_states + basef + (size_t)p * Nn + np * 2);
        S0 = fmaf(f, S0, st.x);
        S1 = fmaf(f, S1, st.y);
    }
}

// ---------------- 7) Y_off via HMMA ----------------
#define KY_C   0
#define KY_S   16384
#define KY_EQ  32768
#define KY_SMEM 33280

__global__ __launch_bounds__(256) void k_yoff() {
    extern __shared__ unsigned char smy[];
    uint32_t sb = smem_u32(smy);
    float* Eq = (float*)(smy + KY_EQ);

    int c = blockIdx.x, h = blockIdx.y, b = blockIdx.z;
    int t = threadIdx.x, lane = t & 31, wid = t >> 5;
    size_t rowbase = ((size_t)(b * Ln + c * Qn)) * CONVD;
    size_t sbase_b = ((size_t)(b * Hn + h) * NCn + c) * 16384;

    for (int i = t; i < 64 * 64; i += 256) {
        int q = i >> 6, cp = i & 63;
        size_t g = rowbase + (size_t)q * CONVD + DINn + Nn + cp * 2;
        uint32_t cu = *(const uint32_t*)(g_xbc + g);
        int chunk = cp >> 5;
        uint32_t off = chunk * 8192 + swz128((uint32_t)(q * 128 + (cp & 31) * 4));
        *(uint32_t*)(smy + KY_C + off) = cu;
    }
    {
        const uint4* src = (const uint4*)(g_statein + sbase_b);
        uint4* dst = (uint4*)(smy + KY_S);
        #pragma unroll
        for (int i = 0; i < 4; i++) dst[t + i * 256] = src[t + i * 256];
    }
    if (t < Qn)
        Eq[t] = expf(g_acs[(size_t)(b * Ln + c * Qn + t) * Hn + h]);
    __syncthreads();

    int wq = wid & 3, ws = wid >> 2;
    int rA = wq * 16 + (lane & 7) + ((lane >> 3) & 1) * 8;
    int cA = ((lane >> 4) & 1) * 16;
    int rB = ws * 32 + (lane & 7) + ((lane >> 4) & 1) * 8;
    int cB = ((lane >> 3) & 1) * 16;

    float acc[4][4];
    #pragma unroll
    for (int i = 0; i < 4; i++)
        #pragma unroll
        for (int j = 0; j < 4; j++) acc[i][j] = 0.f;
    #pragma unroll
    for (int ch = 0; ch < 2; ch++) {
        #pragma unroll
        for (int k = 0; k < 4; k++) {
            uint32_t ah[4];
            LDSMX4(ah, sb + KY_C + ch * 8192 + swz128((uint32_t)(rA * 128 + k * 32 + cA)));
            uint32_t bh[2][4];
            #pragma unroll
            for (int ib = 0; ib < 2; ib++)
                LDSMX4(bh[ib], sb + KY_S + ch * 8192 +
                       swz128((uint32_t)((rB + ib * 16) * 128 + k * 32 + cB)));
            #pragma unroll
            for (int ib = 0; ib < 2; ib++)
                #pragma unroll
                for (int hf = 0; hf < 2; hf++)
                    MMA_FP16(acc[ib * 2 + hf], ah, bh[ib][2 * hf], bh[ib][2 * hf + 1]);
        }
    }
    int q0 = wq * 16 + (lane >> 2);
    int p0 = ws * 32 + (lane & 3) * 2;
    #pragma unroll
    for (int nt = 0; nt < 4; nt++) {
        int p = p0 + nt * 8;
        #pragma unroll
        for (int r2 = 0; r2 < 2; r2++) {
            int q = q0 + r2 * 8;
            float e = Eq[q];
            float* dst = g_y + ((size_t)(b * Ln + c * Qn + q) * Hn + h) * Pn + p;
            float2 cur = *(float2*)dst;
            cur.x += e * acc[nt][r2 * 2 + 0];
            cur.y += e * acc[nt][r2 * 2 + 1];
            *(float2*)dst = cur;
        }
    }
}

// ---------------- 8) gated rmsnorm -> fp16 A tiles ----------------
__global__ __launch_bounds__(256) void k_gatenorm_split(
    const float* __restrict__ gw, unsigned char* __restrict__ Af) {
    size_t row = blockIdx.x;
    int t = threadIdx.x;
    const float4* py = (const float4*)(g_y + row * DINn);
    const float4* pz = (const float4*)(g_proj + row * PROJW);
    float v[16];
    float ss = 0.f;
    #pragma unroll
    for (int i = 0; i < 4; i++) {
        float4 y4 = py[t * 4 + i];
        float4 z4 = pz[t * 4 + i];
        float x0 = y4.x * siluf(z4.x);
        float x1 = y4.y * siluf(z4.y);
        float x2 = y4.z * siluf(z4.z);
        float x3 = y4.w * siluf(z4.w);
        v[i * 4 + 0] = x0; v[i * 4 + 1] = x1; v[i * 4 + 2] = x2; v[i * 4 + 3] = x3;
        ss += x0 * x0 + x1 * x1 + x2 * x2 + x3 * x3;
    }
    float tot = block_reduce_sum(ss);
    float inv = rsqrtf(tot / (float)DINn + EPSf);
    int mt = (int)(row >> 7), r = (int)(row & 127);
    size_t tb = (size_t)mt * NCH2 * A_CH;
    #pragma unroll
    for (int j = 0; j < 8; j++) {
        int k = t * 16 + j * 2;
        uint32_t u = pack2h(v[j * 2] * inv * gw[k], v[j * 2 + 1] * inv * gw[k + 1]);
        int kc = k >> 6, cc = k & 63;
        size_t off = tb + (size_t)kc * A_CH + swz128((uint32_t)(r * 128 + cc * 2));
        *(uint32_t*)(Af + off) = u;
    }
}

// ---------------- launch ----------------
extern "C" void kernel_launch(void* const* d_in, const int* in_sizes, int n_in,
                              void* d_out, int out_size) {
    const float* hs   = (const float*)d_in[0];
    const float* res  = (const float*)d_in[1];
    const float* nw   = (const float*)d_in[2];
    const float* ipw  = (const float*)d_in[3];
    const float* cw   = (const float*)d_in[4];
    const float* cb   = (const float*)d_in[5];
    const float* alog = (const float*)d_in[6];
    const float* dtb  = (const float*)d_in[7];
    const float* dsk  = (const float*)d_in[8];
    const float* gnw  = (const float*)d_in[9];
    const float* opw  = (const float*)d_in[10];
    float* out = (float*)d_out;

    void *pproj, *pAf, *pBf, *pyfb;
    cudaGetSymbolAddress(&pproj, g_proj);
    cudaGetSymbolAddress(&pAf, g_Af);
    cudaGetSymbolAddress(&pBf, g_Bf);
    cudaGetSymbolAddress(&pyfb, g_y);

    float* resid_ptr = ((size_t)out_size >= 2ull * BLn * Dn)
                           ? out + (size_t)BLn * Dn
                           : (float*)pyfb;

    const int SMEM_GEMM = 1024 + NSTAGE * (16384 + 32768) + 64;
    cudaFuncSetAttribute(k_chunk, cudaFuncAttributeMaxDynamicSharedMemorySize, KC_SMEM);
    cudaFuncSetAttribute(k_yoff,  cudaFuncAttributeMaxDynamicSharedMemorySize, KY_SMEM);
    cudaFuncSetAttribute(gemm_mma_fp16, cudaFuncAttributeMaxDynamicSharedMemorySize, SMEM_GEMM);

    k_add_rmsnorm_split<<<BLn, 256>>>(hs, res, nw, resid_ptr, (unsigned char*)pAf);
    k_dtproj<<<BLn / 64, 256>>>(ipw, dtb, alog);

    {
        dim3 grid(PROJW / 32, Dn / 64);
        k_splitB<<<grid, 256>>>(ipw, (unsigned char*)pBf, PROJW, NCH1);
    }
    {
        dim3 grid(NT1, MTil);
        gemm_mma_fp16<<<grid, 512, SMEM_GEMM>>>(
            (const unsigned char*)pAf, (const unsigned char*)pBf,
            (float*)pproj, PROJW, NCH1);
    }

    k_conv2<<<Bn * 128 * 17, 256>>>(cw, cb);

    {
        dim3 grid(NCn, Hn, Bn);
        k_chunk<<<grid, 256, KC_SMEM>>>(dsk);
    }
    {
        dim3 grid(Bn * Hn, 16);
        k_scan<<<grid, 256>>>();
    }
    {
        dim3 grid(NCn, Hn, Bn);
        k_yoff<<<grid, 256, KY_SMEM>>>();
    }

    k_gatenorm_split<<<BLn, 256>>>(gnw, (unsigned char*)pAf);

    {
        dim3 grid(Dn / 32, DINn / 64);
        k_splitB<<<grid, 256>>>(opw, (unsigned char*)pBf, Dn, NCH2);
    }
    {
        dim3 grid(Dn / 256, MTil);
        gemm_mma_fp16<<<grid, 512, SMEM_GEMM>>>(
            (const unsigned char*)pAf, (const unsigned char*)pBf,
            out, Dn, NCH2);
    }
}

// round 17
// speedup vs baseline: 1.2004x; 1.2004x over previous
#include <cuda_runtime.h>
#include <cuda_fp16.h>
#include <math.h>
#include <stdint.h>

// ---------------- problem constants ----------------
#define Bn    2
#define Ln    2048
#define Dn    2048
#define DINn  4096
#define Nn    128
#define Hn    64
#define Pn    64
#define Kc    4
#define CONVD 4352            // DIN + 2*G*N
#define Qn    64
#define NCn   32
#define PROJW 8512            // 2*DIN + 2*G*N + H
#define DTOFF 8448            // DIN + CONVD
#define BLn   (Bn*Ln)         // 4096
#define EPSf  1e-5f

// GEMM tiling: 128(M) x 256(N) block tile, BK=64, 512 threads, fp16 single-pass
#define A_CH  16384
#define B_CH  32768
#define NSTAGE 4

#define NCH1  32
#define NT1   33              // 33*256 = 8448: z + xBC only (dt handled by k_dtproj)
#define NTB1  34
#define NCH2  64
#define MTil  32
#define KSPL  8               // dtproj split-K factor

// ---------------- scratch ----------------
__device__ float g_h[(size_t)BLn*Dn];
__device__ float g_proj[(size_t)BLn*PROJW];
__device__ __half g_xbc[(size_t)BLn*CONVD];
__device__ float g_dt[(size_t)BLn*Hn];
__device__ float g_a[(size_t)BLn*Hn];
__device__ float g_acs[(size_t)BLn*Hn];
__device__ float g_csum[(size_t)Bn*Hn*NCn];
__device__ float g_states[(size_t)Bn*Hn*NCn*Pn*Nn];
__device__ __align__(16) unsigned char g_statein[(size_t)Bn*Hn*NCn*16384]; // fp16 swizzled tiles
__device__ float g_y[(size_t)BLn*DINn];
__device__ float g_dtp[(size_t)KSPL*BLn*Hn];          // dtproj split-K partials

__device__ __align__(1024) unsigned char g_Af[(size_t)MTil*NCH2*A_CH];
__device__ __align__(1024) unsigned char g_Bf[(size_t)NTB1*NCH1*B_CH];

// ---------------- PTX helpers ----------------
__device__ __forceinline__ uint32_t smem_u32(const void* p) {
    uint32_t a;
    asm("{ .reg .u64 t; cvta.to.shared.u64 t, %1; cvt.u32.u64 %0, t; }" : "=r"(a) : "l"(p));
    return a;
}
__device__ __forceinline__ uint32_t swz128(uint32_t o) { return o ^ ((o >> 3) & 0x70); }

#define MBAR_INIT(a, c) \
    asm volatile("mbarrier.init.shared.b64 [%0], %1;" :: "r"(a), "r"(c) : "memory")
#define MBAR_EXPECT_TX(a, b) \
    asm volatile("mbarrier.arrive.expect_tx.shared.b64 _, [%0], %1;" :: "r"(a), "r"(b) : "memory")
#define MBAR_WAIT(a, ph) do { \
    uint32_t _m = (a); uint32_t _p = (ph); uint32_t _d; \
    asm volatile("{\n\t.reg .pred p;\n\t" \
        "mbarrier.try_wait.parity.acquire.cta.shared::cta.b64 p, [%1], %2;\n\t" \
        "selp.b32 %0, 1, 0, p;\n\t}" : "=r"(_d) : "r"(_m), "r"(_p) : "memory"); \
    if (!_d) { \
        asm volatile("{\n\t.reg .pred P1;\n\t" \
            "WL_%=:\n\t" \
            "mbarrier.try_wait.parity.acquire.cta.shared::cta.b64 P1, [%0], %1, 0x989680;\n\t" \
            "@P1 bra.uni WD_%=;\n\t" \
            "bra.uni WL_%=;\n\t" \
            "WD_%=:\n\t}" :: "r"(_m), "r"(_p) : "memory"); \
    } \
} while (0)

#define BULK_LD(sa, gp, bytes, mb) \
    asm volatile("cp.async.bulk.shared::cluster.global.mbarrier::complete_tx::bytes [%0], [%1], %2, [%3];" \
        :: "r"(sa), "l"(gp), "r"(bytes), "r"(mb) : "memory")

#define LDSMX4(r, addr) \
    asm volatile("ldmatrix.sync.aligned.m8n8.x4.shared.b16 {%0,%1,%2,%3}, [%4];" \
        : "=r"((r)[0]), "=r"((r)[1]), "=r"((r)[2]), "=r"((r)[3]) : "r"(addr))

#define MMA_FP16(d, a, b0, b1) \
    asm volatile("mma.sync.aligned.m16n8k16.row.col.f32.f16.f16.f32 " \
        "{%0,%1,%2,%3}, {%4,%5,%6,%7}, {%8,%9}, {%0,%1,%2,%3};" \
        : "+f"((d)[0]), "+f"((d)[1]), "+f"((d)[2]), "+f"((d)[3]) \
        : "r"((a)[0]), "r"((a)[1]), "r"((a)[2]), "r"((a)[3]), "r"(b0), "r"(b1))

// ---------------- misc helpers ----------------
__device__ __forceinline__ float block_reduce_sum(float v) {
    __shared__ float red[32];
    int lane = threadIdx.x & 31, wid = threadIdx.x >> 5;
    #pragma unroll
    for (int o = 16; o; o >>= 1) v += __shfl_down_sync(0xffffffffu, v, o);
    if (lane == 0) red[wid] = v;
    __syncthreads();
    v = (threadIdx.x < (blockDim.x >> 5)) ? red[threadIdx.x] : 0.f;
    if (wid == 0) {
        #pragma unroll
        for (int o = 16; o; o >>= 1) v += __shfl_down_sync(0xffffffffu, v, o);
        if (lane == 0) red[0] = v;
    }
    __syncthreads();
    return red[0];
}
__device__ __forceinline__ float siluf(float x) { return x / (1.f + expf(-x)); }

__device__ __forceinline__ uint32_t pack2h(float x0, float x1) {
    __half h0 = __float2half_rn(x0);
    __half h1 = __float2half_rn(x1);
    return ((uint32_t)__half_as_ushort(h1) << 16) | __half_as_ushort(h0);
}

// ---------------- 1) resid + rmsnorm -> fp32 g_h + fp16 A tiles ----------------
__global__ __launch_bounds__(256) void k_add_rmsnorm_split(
    const float* __restrict__ hs, const float* __restrict__ res,
    const float* __restrict__ w, float* __restrict__ resid_out,
    unsigned char* __restrict__ Af) {
    size_t row = blockIdx.x;
    int t = threadIdx.x;
    const float4* ph = (const float4*)(hs + row * Dn);
    const float4* pr = (const float4*)(res + row * Dn);
    float4* po = (float4*)(resid_out + row * Dn);
    float v[8];
    float ss = 0.f;
    #pragma unroll
    for (int i = 0; i < 2; i++) {
        float4 a = ph[t * 2 + i], b = pr[t * 2 + i];
        float4 x = make_float4(a.x + b.x, a.y + b.y, a.z + b.z, a.w + b.w);
        po[t * 2 + i] = x;
        v[i * 4 + 0] = x.x; v[i * 4 + 1] = x.y; v[i * 4 + 2] = x.z; v[i * 4 + 3] = x.w;
        ss += x.x * x.x + x.y * x.y + x.z * x.z + x.w * x.w;
    }
    float tot = block_reduce_sum(ss);
    float inv = rsqrtf(tot / (float)Dn + EPSf);
    int mt = (int)(row >> 7), r = (int)(row & 127);
    size_t tb = (size_t)mt * NCH1 * A_CH;
    float4* gh = (float4*)(g_h + row * Dn);
    #pragma unroll
    for (int i = 0; i < 2; i++) {
        float4 x = make_float4(v[i*4]*inv*w[t*8+i*4], v[i*4+1]*inv*w[t*8+i*4+1],
                               v[i*4+2]*inv*w[t*8+i*4+2], v[i*4+3]*inv*w[t*8+i*4+3]);
        gh[t * 2 + i] = x;
        v[i*4] = x.x; v[i*4+1] = x.y; v[i*4+2] = x.z; v[i*4+3] = x.w;
    }
    #pragma unroll
    for (int j = 0; j < 4; j++) {
        int k = t * 8 + j * 2;
        uint32_t u = pack2h(v[j * 2], v[j * 2 + 1]);
        int kc = k >> 6, c = k & 63;
        size_t off = tb + (size_t)kc * A_CH + swz128((uint32_t)(r * 128 + c * 2));
        *(uint32_t*)(Af + off) = u;
    }
}

// ---------------- weight transpose to fp16 ----------------
__global__ __launch_bounds__(256) void k_splitB(
    const float* __restrict__ W, unsigned char* __restrict__ Bf, int Nreal, int nch) {
    __shared__ float tile[64][33];
    int kb = blockIdx.y * 64;
    int n0 = blockIdx.x * 32;
    int t = threadIdx.x;
    int tx = t & 31, ty = t >> 5;
    #pragma unroll
    for (int i = 0; i < 8; i++) {
        int k = ty + i * 8;
        tile[k][tx] = W[(size_t)(kb + k) * Nreal + n0 + tx];
    }
    __syncthreads();
    int kc = kb >> 6;
    #pragma unroll
    for (int j = 0; j < 4; j++) {
        int nl = ty * 4 + j;
        int n = n0 + nl;
        uint32_t u = pack2h(tile[tx * 2][nl], tile[tx * 2 + 1][nl]);
        int nt = n >> 8, r = n & 255;
        size_t base = ((size_t)(nt * nch + kc)) * B_CH;
        size_t off = base + swz128((uint32_t)(r * 128 + tx * 4));
        *(uint32_t*)(Bf + off) = u;
    }
}

// ---------------- fp16 GEMM: 4-stage, paired-chunk (R13-proven) ----------------
__global__ __launch_bounds__(512) void gemm_mma_fp16(
    const unsigned char* __restrict__ Af, const unsigned char* __restrict__ Bf,
    float* __restrict__ C, int Nreal, int nch) {
    constexpr int STGB = 16384 + 32768;
    extern __shared__ unsigned char smg[];
    uint32_t sb = (smem_u32(smg) + 1023) & ~1023u;
    uint32_t ctrl = sb + NSTAGE * STGB;
    int t = threadIdx.x, lane = t & 31, wid = t >> 5;
    int bx = blockIdx.x, by = blockIdx.y;

    if (t == 0) {
        MBAR_INIT(ctrl + 0, 1); MBAR_INIT(ctrl + 8, 1);
        MBAR_INIT(ctrl + 16, 1); MBAR_INIT(ctrl + 24, 1);
    }
    __syncthreads();

    const unsigned char* Ap = Af + (size_t)by * nch * A_CH;
    const unsigned char* Bp = Bf + (size_t)bx * nch * B_CH;

    int wm = wid & 1, wn = wid >> 1;
    int rowA = wm * 64 + (lane & 7) + ((lane >> 3) & 1) * 8;
    int colA = ((lane >> 4) & 1) * 16;
    int rowB = wn * 32 + (lane & 7) + ((lane >> 4) & 1) * 8;
    int colB = ((lane >> 3) & 1) * 16;

    float acc[4][4][4];
    #pragma unroll
    for (int i = 0; i < 4; i++)
        #pragma unroll
        for (int j = 0; j < 4; j++)
            #pragma unroll
            for (int q = 0; q < 4; q++) acc[i][j][q] = 0.f;

    if (t == 0) {
        #pragma unroll
        for (int pc = 0; pc < 4; pc++) {
            MBAR_EXPECT_TX(ctrl + pc * 8, STGB);
            BULK_LD(sb + pc * STGB + 0,     Ap + (size_t)pc * A_CH, A_CH, ctrl + pc * 8);
            BULK_LD(sb + pc * STGB + 16384, Bp + (size_t)pc * B_CH, B_CH, ctrl + pc * 8);
        }
    }
    int ph[NSTAGE] = {0, 0, 0, 0};
    for (int kc = 0; kc < nch; kc += 2) {
        #pragma unroll
        for (int half = 0; half < 2; half++) {
            int slot = (kc + half) % NSTAGE;
            MBAR_WAIT(ctrl + slot * 8, ph[slot]);
            ph[slot] ^= 1;
            uint32_t s = sb + slot * STGB;
            uint32_t sA = s, sB = s + 16384;
            #pragma unroll
            for (int k = 0; k < 4; k++) {
                uint32_t bh[2][4];
                #pragma unroll
                for (int ib = 0; ib < 2; ib++) {
                    uint32_t off = swz128((uint32_t)((rowB + ib * 16) * 128 + k * 32 + colB));
                    LDSMX4(bh[ib], sB + off);
                }
                #pragma unroll
                for (int im = 0; im < 4; im++) {
                    uint32_t ah[4];
                    uint32_t off = swz128((uint32_t)((rowA + im * 16) * 128 + k * 32 + colA));
                    LDSMX4(ah, sA + off);
                    #pragma unroll
                    for (int ib = 0; ib < 2; ib++)
                        #pragma unroll
                        for (int hf = 0; hf < 2; hf++)
                            MMA_FP16(acc[im][ib * 2 + hf], ah, bh[ib][2 * hf], bh[ib][2 * hf + 1]);
                }
            }
        }
        __syncthreads();
        if (t == 0) {
            #pragma unroll
            for (int half = 0; half < 2; half++) {
                int nc = kc + 4 + half;
                if (nc < nch) {
                    int ns = nc % NSTAGE;
                    uint32_t d = sb + ns * STGB;
                    uint32_t mb = ctrl + ns * 8;
                    MBAR_EXPECT_TX(mb, STGB);
                    BULK_LD(d + 0,     Ap + (size_t)nc * A_CH, A_CH, mb);
                    BULK_LD(d + 16384, Bp + (size_t)nc * B_CH, B_CH, mb);
                }
            }
        }
    }

    int mBase = by * 128 + wm * 64;
    int nBase = bx * 256 + wn * 32;
    #pragma unroll
    for (int im = 0; im < 4; im++) {
        #pragma unroll
        for (int in = 0; in < 4; in++) {
            int r = mBase + im * 16 + (lane >> 2);
            int c = nBase + in * 8 + (lane & 3) * 2;
            if (c < Nreal) {
                float2 v0 = make_float2(acc[im][in][0], acc[im][in][1]);
                float2 v1 = make_float2(acc[im][in][2], acc[im][in][3]);
                *(float2*)(C + (size_t)r * Nreal + c) = v0;
                *(float2*)(C + (size_t)(r + 8) * Nreal + c) = v1;
            }
        }
    }
}

// ---------------- dt projection, split-K partials (fp32 exact within slice) ----------------
__global__ __launch_bounds__(256) void k_dtproj_part(const float* __restrict__ ipw) {
    __shared__ float sh[64][68];
    __shared__ float sw[64][68];
    int m0 = blockIdx.x * 64;
    int kslice = blockIdx.y;           // 0..KSPL-1, K range [kslice*256, kslice*256+256)
    int t = threadIdx.x;
    int tm = t >> 4, tn = t & 15;
    float acc[4][4];
    #pragma unroll
    for (int i = 0; i < 4; i++)
        #pragma unroll
        for (int j = 0; j < 4; j++) acc[i][j] = 0.f;

    int kbeg = kslice * (Dn / KSPL);
    int kend = kbeg + (Dn / KSPL);
    for (int kb = kbeg; kb < kend; kb += 64) {
        #pragma unroll
        for (int i = 0; i < 16; i++) {
            int idx = t + i * 256;
            int m = idx >> 6, kk = idx & 63;
            sh[kk][m] = g_h[(size_t)(m0 + m) * Dn + kb + kk];
        }
        #pragma unroll
        for (int i = 0; i < 16; i++) {
            int idx = t + i * 256;
            int kk = idx >> 6, h = idx & 63;
            sw[kk][h] = ipw[(size_t)(kb + kk) * PROJW + DTOFF + h];
        }
        __syncthreads();
        #pragma unroll 8
        for (int kk = 0; kk < 64; kk++) {
            float4 ar = *(const float4*)&sh[kk][tm * 4];
            float4 br = *(const float4*)&sw[kk][tn * 4];
            float a4[4] = {ar.x, ar.y, ar.z, ar.w};
            float b4[4] = {br.x, br.y, br.z, br.w};
            #pragma unroll
            for (int i = 0; i < 4; i++)
                #pragma unroll
                for (int j = 0; j < 4; j++) acc[i][j] = fmaf(a4[i], b4[j], acc[i][j]);
        }
        __syncthreads();
    }
    size_t pbase = (size_t)kslice * BLn * Hn;
    #pragma unroll
    for (int i = 0; i < 4; i++) {
        int m = m0 + tm * 4 + i;
        #pragma unroll
        for (int j = 0; j < 4; j++) {
            int h = tn * 4 + j;
            g_dtp[pbase + (size_t)m * Hn + h] = acc[i][j];
        }
    }
}

// ---------------- dt finalize: sum partials + bias + softplus ----------------
__global__ __launch_bounds__(256) void k_dtfin(
    const float* __restrict__ dtb, const float* __restrict__ alog) {
    int idx = blockIdx.x * 256 + threadIdx.x;   // over BLn*Hn
    int h = idx & (Hn - 1);
    float s = 0.f;
    #pragma unroll
    for (int k = 0; k < KSPL; k++)
        s += g_dtp[(size_t)k * BLn * Hn + idx];
    float x = s + dtb[h];
    float sp = (x > 20.f) ? x : log1pf(expf(x));
    g_dt[idx] = sp;
    g_a[idx] = -expf(alog[h]) * sp;
}

// ---------------- 3) causal depthwise conv -> fp16 g_xbc ----------------
__global__ __launch_bounds__(256) void k_conv2(
    const float* __restrict__ cw, const float* __restrict__ cb) {
    int bid = blockIdx.x;
    int c = (bid % 17) * 256 + threadIdx.x;
    int lblk = (bid / 17) & 127;
    int b = bid / (17 * 128);
    int l0 = lblk * 16;
    float w0 = cw[c * 4 + 0], w1 = cw[c * 4 + 1], w2 = cw[c * 4 + 2], w3 = cw[c * 4 + 3];
    float bias = cb[c];
    float x[19];
    #pragma unroll
    for (int i = 0; i < 19; i++) {
        int ls = l0 - 3 + i;
        x[i] = (ls >= 0) ? g_proj[((size_t)(b * Ln + ls)) * PROJW + DINn + c] : 0.f;
    }
    #pragma unroll
    for (int j = 0; j < 16; j++) {
        float acc = fmaf(w0, x[j], fmaf(w1, x[j + 1], fmaf(w2, x[j + 2], fmaf(w3, x[j + 3], bias))));
        g_xbc[((size_t)(b * Ln + l0 + j)) * CONVD + c] = __float2half_rn(siluf(acc));
    }
}

// ---------------- 5) per-chunk SSD via HMMA ----------------
#define KC_B   0
#define KC_C   16384
#define KC_BT  32768
#define KC_XT  49152
#define KC_XDT 57344
#define KC_M   65536
#define KC_ACS 73728
#define KC_DEC 73984
#define KC_WS  74240
#define KC_SMEM 74496

__global__ __launch_bounds__(256) void k_chunk(const float* __restrict__ dskip) {
    extern __shared__ unsigned char smc[];
    uint32_t sb = smem_u32(smc);
    float* Acs = (float*)(smc + KC_ACS);
    float* Dec = (float*)(smc + KC_DEC);
    float* WS  = (float*)(smc + KC_WS);

    int c = blockIdx.x, h = blockIdx.y, b = blockIdx.z;
    int t = threadIdx.x, lane = t & 31, wid = t >> 5;
    size_t rowbase = ((size_t)(b * Ln + c * Qn)) * CONVD;

    for (int i = t; i < 64 * 64; i += 256) {
        int s = i >> 6, cp = i & 63;
        size_t g = rowbase + (size_t)s * CONVD + DINn + cp * 2;
        uint32_t bu = *(const uint32_t*)(g_xbc + g);
        uint32_t cu = *(const uint32_t*)(g_xbc + g + Nn);
        int chunk = cp >> 5;
        uint32_t off = chunk * 8192 + swz128((uint32_t)(s * 128 + (cp & 31) * 4));
        *(uint32_t*)(smc + KC_B + off) = bu;
        *(uint32_t*)(smc + KC_C + off) = cu;
    }
    float xv = 0.f;
    if (t < Qn) {
        xv = g_a[(size_t)(b * Ln + c * Qn + t) * Hn + h];
        #pragma unroll
        for (int o = 1; o < 32; o <<= 1) {
            float y = __shfl_up_sync(0xffffffffu, xv, o);
            if ((t & 31) >= o) xv += y;
        }
        if ((t & 31) == 31) WS[t >> 5] = xv;
    }
    __syncthreads();
    if (t < Qn) {
        if (t >= 32) xv += WS[0];
        Acs[t] = xv;
    }
    __syncthreads();
    if (t < Qn) {
        float aq = Acs[t];
        Dec[t] = expf(Acs[Qn - 1] - aq);
        g_acs[(size_t)(b * Ln + c * Qn + t) * Hn + h] = aq;
        if (t == Qn - 1) g_csum[(size_t)(b * Hn + h) * NCn + c] = aq;
    }
    for (int i = t; i < 128 * 32; i += 256) {
        int n = i >> 5, q2 = (i & 31) * 2;
        int chunk = n >> 6, nc = n & 63;
        __half b0 = *(const __half*)(smc + KC_B + chunk * 8192 +
                                     swz128((uint32_t)(q2 * 128 + nc * 2)));
        __half b1 = *(const __half*)(smc + KC_B + chunk * 8192 +
                                     swz128((uint32_t)((q2 + 1) * 128 + nc * 2)));
        uint32_t u = ((uint32_t)__half_as_ushort(b1) << 16) | __half_as_ushort(b0);
        *(uint32_t*)(smc + KC_BT + swz128((uint32_t)(n * 128 + q2 * 2))) = u;
    }
    __syncthreads();
    for (int i = t; i < 64 * 32; i += 256) {
        int p = i & 63, sp = (i >> 6) * 2;
        float x0 = __half2float(g_xbc[rowbase + (size_t)sp * CONVD + h * Pn + p])
                 * g_dt[(size_t)(b * Ln + c * Qn + sp) * Hn + h];
        float x1 = __half2float(g_xbc[rowbase + (size_t)(sp + 1) * CONVD + h * Pn + p])
                 * g_dt[(size_t)(b * Ln + c * Qn + sp + 1) * Hn + h];
        uint32_t off = swz128((uint32_t)(p * 128 + sp * 2));
        *(uint32_t*)(smc + KC_XT + off) = pack2h(x0, x1);
        *(uint32_t*)(smc + KC_XDT + off) = pack2h(x0 * Dec[sp], x1 * Dec[sp + 1]);
    }
    __syncthreads();

    int wq = wid & 3, ws = wid >> 2;
    int rA = wq * 16 + (lane & 7) + ((lane >> 3) & 1) * 8;
    int cA = ((lane >> 4) & 1) * 16;
    int rB = ws * 32 + (lane & 7) + ((lane >> 4) & 1) * 8;
    int cB = ((lane >> 3) & 1) * 16;

    float mAcc[4][4];
    #pragma unroll
    for (int i = 0; i < 4; i++)
        #pragma unroll
        for (int j = 0; j < 4; j++) mAcc[i][j] = 0.f;
    #pragma unroll
    for (int ch = 0; ch < 2; ch++) {
        #pragma unroll
        for (int k = 0; k < 4; k++) {
            uint32_t ah[4];
            LDSMX4(ah, sb + KC_C + ch * 8192 + swz128((uint32_t)(rA * 128 + k * 32 + cA)));
            uint32_t bh[2][4];
            #pragma unroll
            for (int ib = 0; ib < 2; ib++)
                LDSMX4(bh[ib], sb + KC_B + ch * 8192 +
                       swz128((uint32_t)((rB + ib * 16) * 128 + k * 32 + cB)));
            #pragma unroll
            for (int ib = 0; ib < 2; ib++)
                #pragma unroll
                for (int hf = 0; hf < 2; hf++)
                    MMA_FP16(mAcc[ib * 2 + hf], ah, bh[ib][2 * hf], bh[ib][2 * hf + 1]);
        }
    }
    {
        int q0 = wq * 16 + (lane >> 2);
        int sc0 = ws * 32 + (lane & 3) * 2;
        #pragma unroll
        for (int nt = 0; nt < 4; nt++) {
            int sc = sc0 + nt * 8;
            #pragma unroll
            for (int r2 = 0; r2 < 2; r2++) {
                int q = q0 + r2 * 8;
                float aq = Acs[q];
                float v0 = (sc <= q)     ? mAcc[nt][r2 * 2 + 0] * expf(aq - Acs[sc])     : 0.f;
                float v1 = (sc + 1 <= q) ? mAcc[nt][r2 * 2 + 1] * expf(aq - Acs[sc + 1]) : 0.f;
                *(uint32_t*)(smc + KC_M + swz128((uint32_t)(q * 128 + sc * 2))) = pack2h(v0, v1);
            }
        }
    }
    __syncthreads();

    {
        float yAcc[4][4];
        #pragma unroll
        for (int i = 0; i < 4; i++)
            #pragma unroll
            for (int j = 0; j < 4; j++) yAcc[i][j] = 0.f;
        #pragma unroll
        for (int k = 0; k < 4; k++) {
            uint32_t ah[4];
            LDSMX4(ah, sb + KC_M + swz128((uint32_t)(rA * 128 + k * 32 + cA)));
            uint32_t bh[2][4];
            #pragma unroll
            for (int ib = 0; ib < 2; ib++)
                LDSMX4(bh[ib], sb + KC_XT +
                       swz128((uint32_t)((rB + ib * 16) * 128 + k * 32 + cB)));
            #pragma unroll
            for (int ib = 0; ib < 2; ib++)
                #pragma unroll
                for (int hf = 0; hf < 2; hf++)
                    MMA_FP16(yAcc[ib * 2 + hf], ah, bh[ib][2 * hf], bh[ib][2 * hf + 1]);
        }
        float dsk = dskip[h];
        int q0 = wq * 16 + (lane >> 2);
        int p0 = ws * 32 + (lane & 3) * 2;
        #pragma unroll
        for (int nt = 0; nt < 4; nt++) {
            int p = p0 + nt * 8;
            #pragma unroll
            for (int r2 = 0; r2 < 2; r2++) {
                int q = q0 + r2 * 8;
                __half2 xsh = *(const __half2*)(g_xbc + rowbase + (size_t)q * CONVD + h * Pn + p);
                float2 xs2 = __half22float2(xsh);
                float2 o;
                o.x = yAcc[nt][r2 * 2 + 0] + dsk * xs2.x;
                o.y = yAcc[nt][r2 * 2 + 1] + dsk * xs2.y;
                *(float2*)(g_y + ((size_t)(b * Ln + c * Qn + q) * Hn + h) * Pn + p) = o;
            }
        }
    }

    {
        float sAcc[8][4];
        #pragma unroll
        for (int i = 0; i < 8; i++)
            #pragma unroll
            for (int j = 0; j < 4; j++) sAcc[i][j] = 0.f;
        int rBs = ws * 64 + (lane & 7) + ((lane >> 4) & 1) * 8;
        #pragma unroll
        for (int k = 0; k < 4; k++) {
            uint32_t ah[4];
            LDSMX4(ah, sb + KC_XDT + swz128((uint32_t)(rA * 128 + k * 32 + cA)));
            uint32_t bh[4][4];
            #pragma unroll
            for (int ib = 0; ib < 4; ib++)
                LDSMX4(bh[ib], sb + KC_BT +
                       swz128((uint32_t)((rBs + ib * 16) * 128 + k * 32 + cB)));
            #pragma unroll
            for (int ib = 0; ib < 4; ib++)
                #pragma unroll
                for (int hf = 0; hf < 2; hf++)
                    MMA_FP16(sAcc[ib * 2 + hf], ah, bh[ib][2 * hf], bh[ib][2 * hf + 1]);
        }
        size_t base = ((size_t)(b * Hn + h) * NCn + c) * (Pn * Nn);
        int p0 = wq * 16 + (lane >> 2);
        int n0 = ws * 64 + (lane & 3) * 2;
        #pragma unroll
        for (int nt = 0; nt < 8; nt++) {
            int n = n0 + nt * 8;
            #pragma unroll
            for (int r2 = 0; r2 < 2; r2++) {
                int p = p0 + r2 * 8;
                float2 o = make_float2(sAcc[nt][r2 * 2 + 0], sAcc[nt][r2 * 2 + 1]);
                *(float2*)(g_states + base + (size_t)p * Nn + n) = o;
            }
        }
    }
}

// ---------------- 6) chunk-level scan -> fp16 swizzled statein tiles ----------------
__global__ __launch_bounds__(256) void k_scan() {
    int bh = blockIdx.x;
    int idx = blockIdx.y * 256 + threadIdx.x;
    int p = idx >> 6, np = idx & 63;
    int chn = np >> 5;
    uint32_t soff = chn * 8192 + swz128((uint32_t)(p * 128 + (np & 31) * 4));
    float S0 = 0.f, S1 = 0.f;
    for (int c = 0; c < NCn; c++) {
        size_t basef = ((size_t)bh * NCn + c) * (Pn * Nn);
        size_t baseb = ((size_t)bh * NCn + c) * 16384;
        *(uint32_t*)(g_statein + baseb + soff) = pack2h(S0, S1);
        float f = expf(g_csum[(size_t)bh * NCn + c]);
        float2 st = *(const float2*)(g_states + basef + (size_t)p * Nn + np * 2);
        S0 = fmaf(f, S0, st.x);
        S1 = fmaf(f, S1, st.y);
    }
}

// ---------------- 7) Y_off via HMMA ----------------
#define KY_C   0
#define KY_S   16384
#define KY_EQ  32768
#define KY_SMEM 33280

__global__ __launch_bounds__(256) void k_yoff() {
    extern __shared__ unsigned char smy[];
    uint32_t sb = smem_u32(smy);
    float* Eq = (float*)(smy + KY_EQ);

    int c = blockIdx.x, h = blockIdx.y, b = blockIdx.z;
    int t = threadIdx.x, lane = t & 31, wid = t >> 5;
    size_t rowbase = ((size_t)(b * Ln + c * Qn)) * CONVD;
    size_t sbase_b = ((size_t)(b * Hn + h) * NCn + c) * 16384;

    for (int i = t; i < 64 * 64; i += 256) {
        int q = i >> 6, cp = i & 63;
        size_t g = rowbase + (size_t)q * CONVD + DINn + Nn + cp * 2;
        uint32_t cu = *(const uint32_t*)(g_xbc + g);
        int chunk = cp >> 5;
        uint32_t off = chunk * 8192 + swz128((uint32_t)(q * 128 + (cp & 31) * 4));
        *(uint32_t*)(smy + KY_C + off) = cu;
    }
    {
        const uint4* src = (const uint4*)(g_statein + sbase_b);
        uint4* dst = (uint4*)(smy + KY_S);
        #pragma unroll
        for (int i = 0; i < 4; i++) dst[t + i * 256] = src[t + i * 256];
    }
    if (t < Qn)
        Eq[t] = expf(g_acs[(size_t)(b * Ln + c * Qn + t) * Hn + h]);
    __syncthreads();

    int wq = wid & 3, ws = wid >> 2;
    int rA = wq * 16 + (lane & 7) + ((lane >> 3) & 1) * 8;
    int cA = ((lane >> 4) & 1) * 16;
    int rB = ws * 32 + (lane & 7) + ((lane >> 4) & 1) * 8;
    int cB = ((lane >> 3) & 1) * 16;

    float acc[4][4];
    #pragma unroll
    for (int i = 0; i < 4; i++)
        #pragma unroll
        for (int j = 0; j < 4; j++) acc[i][j] = 0.f;
    #pragma unroll
    for (int ch = 0; ch < 2; ch++) {
        #pragma unroll
        for (int k = 0; k < 4; k++) {
            uint32_t ah[4];
            LDSMX4(ah, sb + KY_C + ch * 8192 + swz128((uint32_t)(rA * 128 + k * 32 + cA)));
            uint32_t bh[2][4];
            #pragma unroll
            for (int ib = 0; ib < 2; ib++)
                LDSMX4(bh[ib], sb + KY_S + ch * 8192 +
                       swz128((uint32_t)((rB + ib * 16) * 128 + k * 32 + cB)));
            #pragma unroll
            for (int ib = 0; ib < 2; ib++)
                #pragma unroll
                for (int hf = 0; hf < 2; hf++)
                    MMA_FP16(acc[ib * 2 + hf], ah, bh[ib][2 * hf], bh[ib][2 * hf + 1]);
        }
    }
    int q0 = wq * 16 + (lane >> 2);
    int p0 = ws * 32 + (lane & 3) * 2;
    #pragma unroll
    for (int nt = 0; nt < 4; nt++) {
        int p = p0 + nt * 8;
        #pragma unroll
        for (int r2 = 0; r2 < 2; r2++) {
            int q = q0 + r2 * 8;
            float e = Eq[q];
            float* dst = g_y + ((size_t)(b * Ln + c * Qn + q) * Hn + h) * Pn + p;
            float2 cur = *(float2*)dst;
            cur.x += e * acc[nt][r2 * 2 + 0];
            cur.y += e * acc[nt][r2 * 2 + 1];
            *(float2*)dst = cur;
        }
    }
}

// ---------------- 8) gated rmsnorm -> fp16 A tiles ----------------
__global__ __launch_bounds__(256) void k_gatenorm_split(
    const float* __restrict__ gw, unsigned char* __restrict__ Af) {
    size_t row = blockIdx.x;
    int t = threadIdx.x;
    const float4* py = (const float4*)(g_y + row * DINn);
    const float4* pz = (const float4*)(g_proj + row * PROJW);
    float v[16];
    float ss = 0.f;
    #pragma unroll
    for (int i = 0; i < 4; i++) {
        float4 y4 = py[t * 4 + i];
        float4 z4 = pz[t * 4 + i];
        float x0 = y4.x * siluf(z4.x);
        float x1 = y4.y * siluf(z4.y);
        float x2 = y4.z * siluf(z4.z);
        float x3 = y4.w * siluf(z4.w);
        v[i * 4 + 0] = x0; v[i * 4 + 1] = x1; v[i * 4 + 2] = x2; v[i * 4 + 3] = x3;
        ss += x0 * x0 + x1 * x1 + x2 * x2 + x3 * x3;
    }
    float tot = block_reduce_sum(ss);
    float inv = rsqrtf(tot / (float)DINn + EPSf);
    int mt = (int)(row >> 7), r = (int)(row & 127);
    size_t tb = (size_t)mt * NCH2 * A_CH;
    #pragma unroll
    for (int j = 0; j < 8; j++) {
        int k = t * 16 + j * 2;
        uint32_t u = pack2h(v[j * 2] * inv * gw[k], v[j * 2 + 1] * inv * gw[k + 1]);
        int kc = k >> 6, cc = k & 63;
        size_t off = tb + (size_t)kc * A_CH + swz128((uint32_t)(r * 128 + cc * 2));
        *(uint32_t*)(Af + off) = u;
    }
}

// ---------------- launch ----------------
extern "C" void kernel_launch(void* const* d_in, const int* in_sizes, int n_in,
                              void* d_out, int out_size) {
    const float* hs   = (const float*)d_in[0];
    const float* res  = (const float*)d_in[1];
    const float* nw   = (const float*)d_in[2];
    const float* ipw  = (const float*)d_in[3];
    const float* cw   = (const float*)d_in[4];
    const float* cb   = (const float*)d_in[5];
    const float* alog = (const float*)d_in[6];
    const float* dtb  = (const float*)d_in[7];
    const float* dsk  = (const float*)d_in[8];
    const float* gnw  = (const float*)d_in[9];
    const float* opw  = (const float*)d_in[10];
    float* out = (float*)d_out;

    void *pproj, *pAf, *pBf, *pyfb;
    cudaGetSymbolAddress(&pproj, g_proj);
    cudaGetSymbolAddress(&pAf, g_Af);
    cudaGetSymbolAddress(&pBf, g_Bf);
    cudaGetSymbolAddress(&pyfb, g_y);

    float* resid_ptr = ((size_t)out_size >= 2ull * BLn * Dn)
                           ? out + (size_t)BLn * Dn
                           : (float*)pyfb;

    const int SMEM_GEMM = 1024 + NSTAGE * (16384 + 32768) + 64;
    cudaFuncSetAttribute(k_chunk, cudaFuncAttributeMaxDynamicSharedMemorySize, KC_SMEM);
    cudaFuncSetAttribute(k_yoff,  cudaFuncAttributeMaxDynamicSharedMemorySize, KY_SMEM);
    cudaFuncSetAttribute(gemm_mma_fp16, cudaFuncAttributeMaxDynamicSharedMemorySize, SMEM_GEMM);

    k_add_rmsnorm_split<<<BLn, 256>>>(hs, res, nw, resid_ptr, (unsigned char*)pAf);

    // dt projection: split-K partials (512 CTAs) + finalize
    {
        dim3 grid(BLn / 64, KSPL);
        k_dtproj_part<<<grid, 256>>>(ipw);
    }
    k_dtfin<<<(BLn * Hn) / 256, 256>>>(dtb, alog);

    {
        dim3 grid(PROJW / 32, Dn / 64);
        k_splitB<<<grid, 256>>>(ipw, (unsigned char*)pBf, PROJW, NCH1);
    }
    {
        dim3 grid(NT1, MTil);
        gemm_mma_fp16<<<grid, 512, SMEM_GEMM>>>(
            (const unsigned char*)pAf, (const unsigned char*)pBf,
            (float*)pproj, PROJW, NCH1);
    }

    k_conv2<<<Bn * 128 * 17, 256>>>(cw, cb);

    {
        dim3 grid(NCn, Hn, Bn);
        k_chunk<<<grid, 256, KC_SMEM>>>(dsk);
    }
    {
        dim3 grid(Bn * Hn, 16);
        k_scan<<<grid, 256>>>();
    }
    {
        dim3 grid(NCn, Hn, Bn);
        k_yoff<<<grid, 256, KY_SMEM>>>();
    }

    k_gatenorm_split<<<BLn, 256>>>(gnw, (unsigned char*)pAf);

    {
        dim3 grid(Dn / 32, DINn / 64);
        k_splitB<<<grid, 256>>>(opw, (unsigned char*)pBf, Dn, NCH2);
    }
    {
        dim3 grid(Dn / 256, MTil);
        gemm_mma_fp16<<<grid, 512, SMEM_GEMM>>>(
            (const unsigned char*)pAf, (const unsigned char*)pBf,
            out, Dn, NCH2);
    }
}